// round 16
// baseline (speedup 1.0000x reference)
#include <cuda_runtime.h>
#include <cuda_bf16.h>
#include <cstdint>

#define Bc 8
#define Hc 160
#define Wc 160
#define HWc (Hc*Wc)

typedef unsigned long long ull;
typedef unsigned short ushort_t;

// scratch (no allocations allowed)
__device__ float g_xt[(size_t)Bc*HWc*64];        // x transposed to [b][hw][c] fp32
__device__ ushort_t g_xbh[(size_t)Bc*HWc*64];    // x bf16 hi, [b][hw][c]
__device__ ushort_t g_xbl[(size_t)Bc*HWc*64];    // x bf16 lo residual
__device__ uint4 g_bfrag[9*4*8*32];              // main B frags (hi.x,hi.y,lo.x,lo.y)
__device__ uint4 g_bfragO[9*4*3*32];             // offset-conv B frags
__device__ float g_inv[64];
__device__ float g_bias2[64];

__device__ __forceinline__ uint32_t smem_u32(const void* p) {
    uint32_t a;
    asm("{ .reg .u64 t; cvta.to.shared.u64 t, %1; cvt.u32.u64 %0, t; }" : "=r"(a) : "l"(p));
    return a;
}
__device__ __forceinline__ unsigned sw128(unsigned off) {
    return off ^ ((off >> 3) & 0x70);
}
__device__ __forceinline__ void ldsm4(uint32_t* r, uint32_t addr) {
    asm volatile("ldmatrix.sync.aligned.m8n8.x4.shared.b16 {%0,%1,%2,%3}, [%4];"
        : "=r"(r[0]), "=r"(r[1]), "=r"(r[2]), "=r"(r[3]) : "r"(addr));
}
__device__ __forceinline__ void mma16816(float* c, const uint32_t* a,
                                         uint32_t b0, uint32_t b1) {
    asm volatile("mma.sync.aligned.m16n8k16.row.col.f32.bf16.bf16.f32 "
        "{%0,%1,%2,%3}, {%4,%5,%6,%7}, {%8,%9}, {%0,%1,%2,%3};"
        : "+f"(c[0]), "+f"(c[1]), "+f"(c[2]), "+f"(c[3])
        : "r"(a[0]), "r"(a[1]), "r"(a[2]), "r"(a[3]), "r"(b0), "r"(b1));
}
// pack (x,y) -> bf16x2 hi + residual bf16x2 lo
__device__ __forceinline__ void split2(float x, float y, uint32_t& hv, uint32_t& lv) {
    asm("cvt.rn.bf16x2.f32 %0, %1, %2;" : "=r"(hv) : "f"(y), "f"(x));
    float hx = __uint_as_float(hv << 16);
    float hy = __uint_as_float(hv & 0xffff0000u);
    float rx = x - hx, ry = y - hy;
    asm("cvt.rn.bf16x2.f32 %0, %1, %2;" : "=r"(lv) : "f"(ry), "f"(rx));
}

// fused kernel dynamic smem layout (bytes)
#define SM_A     0                         // A hi: 256 rows x 128 B (SW128)
#define SM_ALO   32768                     // A lo
#define SM_OFF   65536                     // float[18][256] offsets
#define SM_WT    84992                     // float[2][4][256] meta, double-buffered
#define SM_IDX   93184                     // int[2][4][256]
#define SM_TOTAL 101376

// ---------------------------------------------------------------------------
// prep+transpose combined.
// blocks [0, 3200): transpose x [b][c][hw] -> [b][hw][c] fp32 + bf16 hi/lo.
// blocks [3200, 3236): weight-fragment prep (k = idx/4, part = idx%4) + BN.
// ---------------------------------------------------------------------------
__global__ __launch_bounds__(256) void prep_transpose_kernel(
        const float* __restrict__ x,
        const float* __restrict__ w_dcn,
        const float* __restrict__ b_dcn,
        const float* __restrict__ w_off,
        const float* __restrict__ gamma,
        const float* __restrict__ beta,
        const float* __restrict__ run_mean,
        const float* __restrict__ run_var) {
    __shared__ float sm[64*65];
    int t = threadIdx.x;

    if (blockIdx.x < 3200) {
        int b   = blockIdx.x / 400;
        int hw0 = (blockIdx.x % 400) * 64;
        const float* xb = x + (size_t)b*64*HWc;
        #pragma unroll
        for (int i = 0; i < 16; i++) {
            int c = i*4 + (t>>6);
            int j = t & 63;
            sm[c*65 + j] = xb[(size_t)c*HWc + hw0 + j];
        }
        __syncthreads();
        float* ob = g_xt + ((size_t)b*HWc + hw0)*64;
        ushort_t* oh = g_xbh + ((size_t)b*HWc + hw0)*64;
        ushort_t* ol = g_xbl + ((size_t)b*HWc + hw0)*64;
        #pragma unroll
        for (int i = 0; i < 16; i++) {
            int hw = i*4 + (t>>6);
            int c  = t & 63;
            float v = sm[c*65 + hw];
            ob[hw*64 + c] = v;
            __nv_bfloat16 hb = __float2bfloat16_rn(v);
            float lof = v - __bfloat162float(hb);
            oh[hw*64 + c] = __bfloat16_as_ushort(hb);
            ol[hw*64 + c] = __bfloat16_as_ushort(__float2bfloat16_rn(lof));
        }
        return;
    }

    // ---- weight prep ----
    int idx36 = blockIdx.x - 3200;
    int k = idx36 >> 2;
    int part = idx36 & 3;
    {
        int e = part*256 + t;
        int lane  = e & 31;
        int ntile = (e >> 5) & 7;
        int kstep = e >> 8;
        int o  = ntile*8 + (lane >> 2);
        int c0 = kstep*16 + 2*(lane & 3);
        float w00 = w_dcn[o*576 + (c0  )*9 + k];
        float w01 = w_dcn[o*576 + (c0+1)*9 + k];
        float w10 = w_dcn[o*576 + (c0+8)*9 + k];
        float w11 = w_dcn[o*576 + (c0+9)*9 + k];
        uint32_t h0, l0, h1, l1;
        split2(w00, w01, h0, l0);
        split2(w10, w11, h1, l1);
        int idx = ((k*4 + kstep)*8 + ntile)*32 + lane;
        g_bfrag[idx] = make_uint4(h0, h1, l0, l1);
    }
    {
        int e = part*256 + t;
        if (e < 384) {
            int lane  = e & 31;
            int ntile = (e >> 5) % 3;
            int kstep = e / 96;
            int o  = ntile*8 + (lane >> 2);
            int c0 = kstep*16 + 2*(lane & 3);
            float w00 = 0.f, w01 = 0.f, w10 = 0.f, w11 = 0.f;
            if (o < 18) {
                w00 = w_off[o*576 + (c0  )*9 + k];
                w01 = w_off[o*576 + (c0+1)*9 + k];
                w10 = w_off[o*576 + (c0+8)*9 + k];
                w11 = w_off[o*576 + (c0+9)*9 + k];
            }
            uint32_t h0, l0, h1, l1;
            split2(w00, w01, h0, l0);
            split2(w10, w11, h1, l1);
            int idx = ((k*4 + kstep)*3 + ntile)*32 + lane;
            g_bfragO[idx] = make_uint4(h0, h1, l0, l1);
        }
    }
    if (k == 0 && part == 0 && t < 64) {
        float iv = gamma[t] * rsqrtf(run_var[t] + 1e-5f);
        g_inv[t] = iv;
        g_bias2[t] = b_dcn[t]*iv + beta[t] - run_mean[t]*iv;
    }
}

// ---------------------------------------------------------------------------
// fused: [phase 1] offset conv (implicit GEMM, A copied from pre-split bf16
// hi/lo, 3-pass mma) -> offsets in smem; [phase 2] deform bilinear sampling
// + 3-pass bf16 GEMM + BN + ReLU. Block = 256 px (8x32), 256 thr, 2 CTAs/SM.
// ---------------------------------------------------------------------------
__global__ __launch_bounds__(256, 2) void fused_kernel(
        const float* __restrict__ b_off,
        float* __restrict__ out) {
    extern __shared__ char smem[];
    const uint32_t sbase = smem_u32(smem);
    float* s_off = (float*)(smem + SM_OFF);   // [18][256]
    float* s_wt  = (float*)(smem + SM_WT);    // [2][4][256]
    int*   s_idx = (int*)(smem + SM_IDX);     // [2][4][256]

    const int t    = threadIdx.x;
    const int wid  = t >> 5;
    const int lane = t & 31;
    const int b    = blockIdx.z;
    const int h0   = blockIdx.y * 8;
    const int w0   = blockIdx.x * 32;
    const int sq   = t & 15;       // sampler channel-quad
    const int pg   = t >> 4;       // sampler pixel phase (0..15)

    const float* xtb = g_xt + (size_t)b*HWc*64;
    const ushort_t* xbh = g_xbh + (size_t)b*HWc*64;
    const ushort_t* xbl = g_xbl + (size_t)b*HWc*64;

    // A-frag ldmatrix base coords (constant)
    const int arow = wid*32 + (lane & 7) + ((lane >> 3) & 1)*8;   // + mt*16
    const int acol = (lane >> 4) * 16;                            // + ks*32
    const int prow = lane >> 2;
    const int ocol = 2*(lane & 3);

    // ============================ phase 1: offset conv =====================
    {
        float acc[2][3][4];
        #pragma unroll
        for (int mt = 0; mt < 2; mt++)
            #pragma unroll
            for (int nt = 0; nt < 3; nt++)
                #pragma unroll
                for (int r = 0; r < 4; r++) acc[mt][nt][r] = 0.f;

        #pragma unroll 1
        for (int k = 0; k < 9; k++) {
            __syncthreads();   // A free
            const int ky = k/3 - 1, kx = k%3 - 1;

            // A tile: straight copy of pre-split bf16 hi/lo, zero pad
            #pragma unroll 4
            for (int j = 0; j < 16; j++) {
                int p = pg + 16*j;
                int h = h0 + (p >> 5), w = w0 + (p & 31);
                int hy = h + ky, wx = w + kx;
                uint2 hv = make_uint2(0u, 0u), lv = make_uint2(0u, 0u);
                if (hy >= 0 && hy < Hc && wx >= 0 && wx < Wc) {
                    size_t idx = (size_t)(hy*Wc + wx)*64 + sq*4;
                    hv = *(const uint2*)(xbh + idx);
                    lv = *(const uint2*)(xbl + idx);
                }
                unsigned sw = sw128((unsigned)(p*128 + sq*8));
                *(uint2*)(smem + SM_A   + sw) = hv;
                *(uint2*)(smem + SM_ALO + sw) = lv;
            }
            __syncthreads();

            const uint4* bf = g_bfragO + (size_t)k*384;
            #pragma unroll
            for (int ks = 0; ks < 4; ks++) {
                uint32_t ah[2][4], al[2][4];
                #pragma unroll
                for (int mt = 0; mt < 2; mt++) {
                    unsigned off = sw128((unsigned)((arow + mt*16)*128 + acol + ks*32));
                    ldsm4(ah[mt], sbase + SM_A   + off);
                    ldsm4(al[mt], sbase + SM_ALO + off);
                }
                uint4 bv[3];
                #pragma unroll
                for (int nt = 0; nt < 3; nt++)
                    bv[nt] = __ldg(&bf[(ks*3 + nt)*32 + lane]);
                #pragma unroll
                for (int mt = 0; mt < 2; mt++)
                    #pragma unroll
                    for (int nt = 0; nt < 3; nt++) {
                        mma16816(acc[mt][nt], ah[mt], bv[nt].x, bv[nt].y);
                        mma16816(acc[mt][nt], al[mt], bv[nt].x, bv[nt].y);
                        mma16816(acc[mt][nt], ah[mt], bv[nt].z, bv[nt].w);
                    }
            }
        }

        // epilogue: offsets (+bias) into smem [oc][p]
        #pragma unroll
        for (int nt = 0; nt < 3; nt++) {
            int o0 = nt*8 + ocol;
            if (o0 < 18) {
                float bo0 = b_off[o0], bo1 = b_off[o0+1];
                #pragma unroll
                for (int mt = 0; mt < 2; mt++) {
                    #pragma unroll
                    for (int half = 0; half < 2; half++) {
                        int p = wid*32 + mt*16 + prow + half*8;
                        s_off[o0*256 + p]     = acc[mt][nt][half*2]   + bo0;
                        s_off[(o0+1)*256 + p] = acc[mt][nt][half*2+1] + bo1;
                    }
                }
            }
        }
    }
    __syncthreads();   // s_off complete

    // ============================ phase 2: deform GEMM =====================
    float acc[2][8][4];
    #pragma unroll
    for (int mt = 0; mt < 2; mt++)
        #pragma unroll
        for (int nt = 0; nt < 8; nt++)
            #pragma unroll
            for (int r = 0; r < 4; r++) acc[mt][nt][r] = 0.f;

    // meta(k) compute for pixel t into buffer k&1
    const int mh = h0 + (t >> 5), mw = w0 + (t & 31);
    #define COMPUTE_META(k) do {                                              \
        int buf = (k) & 1;                                                    \
        float oy = s_off[(2*(k)  )*256 + t];                                  \
        float ox = s_off[(2*(k)+1)*256 + t];                                  \
        float py = (float)(mh + (k)/3 - 1) + oy;                              \
        float px = (float)(mw + (k)%3 - 1) + ox;                              \
        float y0 = floorf(py), x0 = floorf(px);                               \
        _Pragma("unroll")                                                     \
        for (int d = 0; d < 4; d++) {                                         \
            float iy = y0 + (float)(d >> 1);                                  \
            float ix = x0 + (float)(d & 1);                                   \
            float wgt = (1.f - fabsf(py - iy)) * (1.f - fabsf(px - ix));      \
            bool valid = (iy >= 0.f) && (iy <= (float)(Hc-1)) &&              \
                         (ix >= 0.f) && (ix <= (float)(Wc-1));                \
            s_wt[buf*1024 + d*256 + t] = valid ? wgt : 0.f;                   \
            int iyc = min(max((int)iy, 0), Hc-1);                             \
            int ixc = min(max((int)ix, 0), Wc-1);                             \
            s_idx[buf*1024 + d*256 + t] = (iyc*Wc + ixc) * 64;                \
        }                                                                     \
    } while (0)

    COMPUTE_META(0);

    #pragma unroll 1
    for (int k = 0; k < 9; k++) {
        __syncthreads();   // A free (prev mma done) + meta[k] ready
        const int buf = k & 1;

        // sampling: gather channel-last fp32, split to bf16 hi/lo, store
        #pragma unroll 4
        for (int j = 0; j < 16; j++) {
            int p = pg + 16*j;
            float ax = 0.f, ay = 0.f, az = 0.f, aw = 0.f;
            #pragma unroll
            for (int d = 0; d < 4; d++) {
                float wg = s_wt[buf*1024 + d*256 + p];
                const float4 v = *(const float4*)(xtb + (size_t)s_idx[buf*1024 + d*256 + p] + sq*4);
                ax += wg*v.x; ay += wg*v.y; az += wg*v.z; aw += wg*v.w;
            }
            uint2 hv, lv;
            split2(ax, ay, hv.x, lv.x);
            split2(az, aw, hv.y, lv.y);
            unsigned sw = sw128((unsigned)(p*128 + sq*8));
            *(uint2*)(smem + SM_A   + sw) = hv;
            *(uint2*)(smem + SM_ALO + sw) = lv;
        }
        __syncthreads();   // A ready

        // overlap: meta for k+1 (other buffer) hidden under mma issue
        if (k < 8) COMPUTE_META(k + 1);

        // GEMM: per k-step load A hi/lo frags + interleaved B frags, 3-pass
        const uint4* bf = g_bfrag + (size_t)k*1024;
        #pragma unroll
        for (int ks = 0; ks < 4; ks++) {
            uint32_t ah[2][4], al[2][4];
            #pragma unroll
            for (int mt = 0; mt < 2; mt++) {
                unsigned off = sw128((unsigned)((arow + mt*16)*128 + acol + ks*32));
                ldsm4(ah[mt], sbase + SM_A   + off);
                ldsm4(al[mt], sbase + SM_ALO + off);
            }
            uint4 bv[8];
            #pragma unroll
            for (int nt = 0; nt < 8; nt++)
                bv[nt] = __ldg(&bf[(ks*8 + nt)*32 + lane]);
            #pragma unroll
            for (int mt = 0; mt < 2; mt++)
                #pragma unroll
                for (int nt = 0; nt < 8; nt++) {
                    mma16816(acc[mt][nt], ah[mt], bv[nt].x, bv[nt].y);
                    mma16816(acc[mt][nt], al[mt], bv[nt].x, bv[nt].y);
                    mma16816(acc[mt][nt], ah[mt], bv[nt].z, bv[nt].w);
                }
        }
    }

    // epilogue: BN fold + ReLU, direct stores
    #pragma unroll
    for (int nt = 0; nt < 8; nt++) {
        int o0 = nt*8 + ocol;
        float iv0 = g_inv[o0],   bs0 = g_bias2[o0];
        float iv1 = g_inv[o0+1], bs1 = g_bias2[o0+1];
        #pragma unroll
        for (int mt = 0; mt < 2; mt++) {
            #pragma unroll
            for (int half = 0; half < 2; half++) {
                int p = wid*32 + mt*16 + prow + half*8;
                int h = h0 + (p >> 5), w = w0 + (p & 31);
                float* ob = out + ((size_t)b*64*Hc + h)*Wc + w;
                float y0 = acc[mt][nt][half*2]   * iv0 + bs0;
                float y1 = acc[mt][nt][half*2+1] * iv1 + bs1;
                ob[(size_t)o0*HWc]     = fmaxf(y0, 0.f);
                ob[(size_t)(o0+1)*HWc] = fmaxf(y1, 0.f);
            }
        }
    }
}

// ---------------------------------------------------------------------------
extern "C" void kernel_launch(void* const* d_in, const int* in_sizes, int n_in,
                              void* d_out, int out_size) {
    const float* x        = (const float*)d_in[0];
    const float* w_off    = (const float*)d_in[1];
    const float* b_off    = (const float*)d_in[2];
    const float* w_dcn    = (const float*)d_in[3];
    const float* b_dcn    = (const float*)d_in[4];
    const float* gamma    = (const float*)d_in[5];
    const float* beta     = (const float*)d_in[6];
    const float* run_mean = (const float*)d_in[7];
    const float* run_var  = (const float*)d_in[8];
    float* out = (float*)d_out;

    cudaFuncSetAttribute(fused_kernel,
                         cudaFuncAttributeMaxDynamicSharedMemorySize, SM_TOTAL);

    dim3 grid(Wc/32, Hc/8, Bc);
    prep_transpose_kernel<<<3236, 256>>>(x, w_dcn, b_dcn, w_off,
                                         gamma, beta, run_mean, run_var);
    fused_kernel<<<grid, 256, SM_TOTAL>>>(b_off, out);
}

// round 17
// speedup vs baseline: 1.7861x; 1.7861x over previous
#include <cuda_runtime.h>
#include <cuda_bf16.h>
#include <cstdint>

#define Bc 8
#define Hc 160
#define Wc 160
#define HWc (Hc*Wc)

typedef unsigned long long ull;

// scratch (no allocations allowed)
__device__ float g_xt[(size_t)Bc*HWc*64];        // x transposed to [b][hw][c]
__device__ uint2 g_bfrag_hi[9*4*8*32];           // main B frags bf16 hi [k][kstep][ntile][lane]
__device__ uint2 g_bfrag_lo[9*4*8*32];           // main B frags bf16 lo
__device__ uint2 g_bfragO_hi[9*4*3*32];          // offset-conv B frags hi
__device__ uint2 g_bfragO_lo[9*4*3*32];          // offset-conv B frags lo
__device__ float g_inv[64];
__device__ float g_bias2[64];

__device__ __forceinline__ uint32_t smem_u32(const void* p) {
    uint32_t a;
    asm("{ .reg .u64 t; cvta.to.shared.u64 t, %1; cvt.u32.u64 %0, t; }" : "=r"(a) : "l"(p));
    return a;
}
__device__ __forceinline__ unsigned sw128(unsigned off) {
    return off ^ ((off >> 3) & 0x70);
}
__device__ __forceinline__ void ldsm4(uint32_t* r, uint32_t addr) {
    asm volatile("ldmatrix.sync.aligned.m8n8.x4.shared.b16 {%0,%1,%2,%3}, [%4];"
        : "=r"(r[0]), "=r"(r[1]), "=r"(r[2]), "=r"(r[3]) : "r"(addr));
}
__device__ __forceinline__ void mma16816(float* c, const uint32_t* a, const uint2 b) {
    asm volatile("mma.sync.aligned.m16n8k16.row.col.f32.bf16.bf16.f32 "
        "{%0,%1,%2,%3}, {%4,%5,%6,%7}, {%8,%9}, {%0,%1,%2,%3};"
        : "+f"(c[0]), "+f"(c[1]), "+f"(c[2]), "+f"(c[3])
        : "r"(a[0]), "r"(a[1]), "r"(a[2]), "r"(a[3]), "r"(b.x), "r"(b.y));
}
// pack (x,y) -> bf16x2 hi + residual bf16x2 lo
__device__ __forceinline__ void split2(float x, float y, uint32_t& hv, uint32_t& lv) {
    asm("cvt.rn.bf16x2.f32 %0, %1, %2;" : "=r"(hv) : "f"(y), "f"(x));
    float hx = __uint_as_float(hv << 16);
    float hy = __uint_as_float(hv & 0xffff0000u);
    float rx = x - hx, ry = y - hy;
    asm("cvt.rn.bf16x2.f32 %0, %1, %2;" : "=r"(lv) : "f"(ry), "f"(rx));
}

// fused kernel dynamic smem layout (bytes).
// Phase 2 regions:
#define SM_OFF   0                         // float[18][256] = 18432
#define SM_WT    18432                     // float[2][4][256] = 8192
#define SM_IDX   26624                     // int[2][4][256] = 8192
#define SM_A     34816                     // phase-2 A hi: 256 x 128 B (SW128)
#define SM_ALO   67584                     // phase-2 A lo
#define SM_TOTAL 100352
// Phase-1 padded tile (overlaps the above; handoffs barrier-separated):
// 340 rows (10 x 34 padded pixels) x 128 B each.
#define PH_AHI   0                         // [0, 43520)
#define PH_ALO   44032                     // [44032, 87552)
#define PH_ROWS  340

// ---------------------------------------------------------------------------
// prep: fold BN; split w_dcn AND w_off to bf16 hi/lo in mma B-fragment layout.
// grid (9, 4): k = blockIdx.x, part = blockIdx.y.
// ---------------------------------------------------------------------------
__global__ void prep_kernel(const float* __restrict__ w_dcn,
                            const float* __restrict__ b_dcn,
                            const float* __restrict__ w_off,
                            const float* __restrict__ gamma,
                            const float* __restrict__ beta,
                            const float* __restrict__ run_mean,
                            const float* __restrict__ run_var) {
    int k = blockIdx.x;
    int part = blockIdx.y;
    int t = threadIdx.x;
    {
        int e = part*256 + t;
        int lane  = e & 31;
        int ntile = (e >> 5) & 7;
        int kstep = e >> 8;
        int o  = ntile*8 + (lane >> 2);
        int c0 = kstep*16 + 2*(lane & 3);
        float w00 = w_dcn[o*576 + (c0  )*9 + k];
        float w01 = w_dcn[o*576 + (c0+1)*9 + k];
        float w10 = w_dcn[o*576 + (c0+8)*9 + k];
        float w11 = w_dcn[o*576 + (c0+9)*9 + k];
        uint32_t h0, l0, h1, l1;
        split2(w00, w01, h0, l0);
        split2(w10, w11, h1, l1);
        int idx = ((k*4 + kstep)*8 + ntile)*32 + lane;
        g_bfrag_hi[idx] = make_uint2(h0, h1);
        g_bfrag_lo[idx] = make_uint2(l0, l1);
    }
    {
        int e = part*256 + t;
        if (e < 384) {
            int lane  = e & 31;
            int ntile = (e >> 5) % 3;
            int kstep = e / 96;
            int o  = ntile*8 + (lane >> 2);
            int c0 = kstep*16 + 2*(lane & 3);
            float w00 = 0.f, w01 = 0.f, w10 = 0.f, w11 = 0.f;
            if (o < 18) {
                w00 = w_off[o*576 + (c0  )*9 + k];
                w01 = w_off[o*576 + (c0+1)*9 + k];
                w10 = w_off[o*576 + (c0+8)*9 + k];
                w11 = w_off[o*576 + (c0+9)*9 + k];
            }
            uint32_t h0, l0, h1, l1;
            split2(w00, w01, h0, l0);
            split2(w10, w11, h1, l1);
            int idx = ((k*4 + kstep)*3 + ntile)*32 + lane;
            g_bfragO_hi[idx] = make_uint2(h0, h1);
            g_bfragO_lo[idx] = make_uint2(l0, l1);
        }
    }
    if (k == 0 && part == 0 && t < 64) {
        float iv = gamma[t] * rsqrtf(run_var[t] + 1e-5f);
        g_inv[t] = iv;
        g_bias2[t] = b_dcn[t]*iv + beta[t] - run_mean[t]*iv;
    }
}

// ---------------------------------------------------------------------------
// transpose x: [b][c][hw] -> [b][hw][c]
// ---------------------------------------------------------------------------
__global__ __launch_bounds__(256) void transpose_kernel(const float* __restrict__ x) {
    __shared__ float sm[64*65];
    int b   = blockIdx.y;
    int hw0 = blockIdx.x * 64;
    int t   = threadIdx.x;
    const float* xb = x + (size_t)b*64*HWc;
    #pragma unroll
    for (int i = 0; i < 16; i++) {
        int c = i*4 + (t>>6);
        int j = t & 63;
        sm[c*65 + j] = xb[(size_t)c*HWc + hw0 + j];
    }
    __syncthreads();
    float* ob = g_xt + ((size_t)b*HWc + hw0)*64;
    #pragma unroll
    for (int i = 0; i < 16; i++) {
        int hw = i*4 + (t>>6);
        int c  = t & 63;
        ob[hw*64 + c] = sm[c*65 + hw];
    }
}

// ---------------------------------------------------------------------------
// fused: [phase 1] offset conv as implicit GEMM over ONE padded 10x34 tile
// (built once, bf16 hi/lo; 9 taps = pure ldsm+mma with per-lane padded-row
// addressing, no rebuilds, no per-tap barriers) -> offsets in smem;
// [phase 2] deform bilinear sampling + 3-pass bf16 GEMM + BN + ReLU
// (round-9 structure). Block = 256 px (8x32), 256 threads, 2 CTAs/SM.
// ---------------------------------------------------------------------------
__global__ __launch_bounds__(256, 2) void fused_kernel(
        const float* __restrict__ b_off,
        float* __restrict__ out) {
    extern __shared__ char smem[];
    const uint32_t sbase = smem_u32(smem);
    float* s_off = (float*)(smem + SM_OFF);   // [18][256]
    float* s_wt  = (float*)(smem + SM_WT);    // [2][4][256]
    int*   s_idx = (int*)(smem + SM_IDX);     // [2][4][256]

    const int t    = threadIdx.x;
    const int wid  = t >> 5;
    const int lane = t & 31;
    const int b    = blockIdx.z;
    const int h0   = blockIdx.y * 8;
    const int w0   = blockIdx.x * 32;
    const int sq   = t & 15;       // sampler channel-quad
    const int pg   = t >> 4;       // sampler pixel phase (0..15)

    const float* xtb = g_xt + (size_t)b*HWc*64;

    // A-frag ldmatrix base coords (constant)
    const int arow = wid*32 + (lane & 7) + ((lane >> 3) & 1)*8;   // + mt*16
    const int acol = (lane >> 4) * 16;                            // + ks*32
    const int prow = lane >> 2;
    const int ocol = 2*(lane & 3);

    // ============================ phase 1: offset conv =====================
    {
        // build padded tile once: 340 rows (10 x 34 pixels) x 16 c-quads
        #pragma unroll 4
        for (int u = t; u < PH_ROWS*16; u += 256) {
            int row  = u >> 4, quad = u & 15;
            int i = row / 34, j = row % 34;
            int hy = h0 - 1 + i, wx = w0 - 1 + j;
            float4 v = make_float4(0.f, 0.f, 0.f, 0.f);
            if (hy >= 0 && hy < Hc && wx >= 0 && wx < Wc)
                v = *(const float4*)(xtb + (size_t)(hy*Wc + wx)*64 + quad*4);
            uint2 hv, lv;
            split2(v.x, v.y, hv.x, lv.x);
            split2(v.z, v.w, hv.y, lv.y);
            unsigned sw = sw128((unsigned)(row*128 + quad*8));
            *(uint2*)(smem + PH_AHI + sw) = hv;
            *(uint2*)(smem + PH_ALO + sw) = lv;
        }
        __syncthreads();

        float acc[2][3][4];
        #pragma unroll
        for (int mt = 0; mt < 2; mt++)
            #pragma unroll
            for (int nt = 0; nt < 3; nt++)
                #pragma unroll
                for (int r = 0; r < 4; r++) acc[mt][nt][r] = 0.f;

        // per-mt padded pixel coords for this lane
        int phm[2], pwm[2];
        #pragma unroll
        for (int mt = 0; mt < 2; mt++) {
            int p = arow + mt*16;
            phm[mt] = p >> 5;
            pwm[mt] = p & 31;
        }

        // 9 taps: pure ldsm + mma (per-lane padded-row addressing)
        #pragma unroll 1
        for (int k = 0; k < 9; k++) {
            const int dy = k/3, dx = k%3;    // 0..2
            int padrow[2];
            #pragma unroll
            for (int mt = 0; mt < 2; mt++)
                padrow[mt] = (phm[mt] + dy)*34 + pwm[mt] + dx;

            const uint2* bfh = g_bfragO_hi + (size_t)k*384;
            const uint2* bfl = g_bfragO_lo + (size_t)k*384;
            #pragma unroll
            for (int ks = 0; ks < 4; ks++) {
                uint32_t ah[2][4], al[2][4];
                #pragma unroll
                for (int mt = 0; mt < 2; mt++) {
                    unsigned off = sw128((unsigned)(padrow[mt]*128 + acol + ks*32));
                    ldsm4(ah[mt], sbase + PH_AHI + off);
                    ldsm4(al[mt], sbase + PH_ALO + off);
                }
                uint2 bh[3], bl[3];
                #pragma unroll
                for (int nt = 0; nt < 3; nt++) {
                    bh[nt] = __ldg(&bfh[(ks*3 + nt)*32 + lane]);
                    bl[nt] = __ldg(&bfl[(ks*3 + nt)*32 + lane]);
                }
                #pragma unroll
                for (int mt = 0; mt < 2; mt++)
                    #pragma unroll
                    for (int nt = 0; nt < 3; nt++) {
                        mma16816(acc[mt][nt], ah[mt], bh[nt]);
                        mma16816(acc[mt][nt], al[mt], bh[nt]);
                        mma16816(acc[mt][nt], ah[mt], bl[nt]);
                    }
            }
        }
        __syncthreads();   // all taps' ldsm done; padded tile region reusable

        // epilogue: offsets (+bias) into smem [oc][p]
        #pragma unroll
        for (int nt = 0; nt < 3; nt++) {
            int o0 = nt*8 + ocol;
            if (o0 < 18) {
                float bo0 = b_off[o0], bo1 = b_off[o0+1];
                #pragma unroll
                for (int mt = 0; mt < 2; mt++) {
                    #pragma unroll
                    for (int half = 0; half < 2; half++) {
                        int p = wid*32 + mt*16 + prow + half*8;
                        s_off[o0*256 + p]     = acc[mt][nt][half*2]   + bo0;
                        s_off[(o0+1)*256 + p] = acc[mt][nt][half*2+1] + bo1;
                    }
                }
            }
        }
    }
    __syncthreads();   // s_off complete

    // ============================ phase 2: deform GEMM =====================
    float acc[2][8][4];
    #pragma unroll
    for (int mt = 0; mt < 2; mt++)
        #pragma unroll
        for (int nt = 0; nt < 8; nt++)
            #pragma unroll
            for (int r = 0; r < 4; r++) acc[mt][nt][r] = 0.f;

    // meta(k) compute for pixel t into buffer k&1
    const int mh = h0 + (t >> 5), mw = w0 + (t & 31);
    #define COMPUTE_META(k) do {                                              \
        int buf = (k) & 1;                                                    \
        float oy = s_off[(2*(k)  )*256 + t];                                  \
        float ox = s_off[(2*(k)+1)*256 + t];                                  \
        float py = (float)(mh + (k)/3 - 1) + oy;                              \
        float px = (float)(mw + (k)%3 - 1) + ox;                              \
        float y0 = floorf(py), x0 = floorf(px);                               \
        _Pragma("unroll")                                                     \
        for (int d = 0; d < 4; d++) {                                         \
            float iy = y0 + (float)(d >> 1);                                  \
            float ix = x0 + (float)(d & 1);                                   \
            float wgt = (1.f - fabsf(py - iy)) * (1.f - fabsf(px - ix));      \
            bool valid = (iy >= 0.f) && (iy <= (float)(Hc-1)) &&              \
                         (ix >= 0.f) && (ix <= (float)(Wc-1));                \
            s_wt[buf*1024 + d*256 + t] = valid ? wgt : 0.f;                   \
            int iyc = min(max((int)iy, 0), Hc-1);                             \
            int ixc = min(max((int)ix, 0), Wc-1);                             \
            s_idx[buf*1024 + d*256 + t] = (iyc*Wc + ixc) * 64;                \
        }                                                                     \
    } while (0)

    COMPUTE_META(0);

    #pragma unroll 1
    for (int k = 0; k < 9; k++) {
        __syncthreads();   // A free (prev mma done) + meta[k] ready
        const int buf = k & 1;

        // sampling: gather channel-last, split to bf16 hi/lo, store swizzled
        #pragma unroll 4
        for (int j = 0; j < 16; j++) {
            int p = pg + 16*j;
            float ax = 0.f, ay = 0.f, az = 0.f, aw = 0.f;
            #pragma unroll
            for (int d = 0; d < 4; d++) {
                float wg = s_wt[buf*1024 + d*256 + p];
                const float4 v = *(const float4*)(xtb + (size_t)s_idx[buf*1024 + d*256 + p] + sq*4);
                ax += wg*v.x; ay += wg*v.y; az += wg*v.z; aw += wg*v.w;
            }
            uint2 hv, lv;
            split2(ax, ay, hv.x, lv.x);
            split2(az, aw, hv.y, lv.y);
            unsigned sw = sw128((unsigned)(p*128 + sq*8));
            *(uint2*)(smem + SM_A   + sw) = hv;
            *(uint2*)(smem + SM_ALO + sw) = lv;
        }
        __syncthreads();   // A ready

        // overlap: meta for k+1 (other buffer) hidden under mma issue
        if (k < 8) COMPUTE_META(k + 1);

        // GEMM: per k-step load A hi/lo frags + B hi/lo frags, 3-pass mma
        const uint2* bfh = g_bfrag_hi + (size_t)k*1024;
        const uint2* bfl = g_bfrag_lo + (size_t)k*1024;
        #pragma unroll
        for (int ks = 0; ks < 4; ks++) {
            uint32_t ah[2][4], al[2][4];
            #pragma unroll
            for (int mt = 0; mt < 2; mt++) {
                unsigned off = sw128((unsigned)((arow + mt*16)*128 + acol + ks*32));
                ldsm4(ah[mt], sbase + SM_A   + off);
                ldsm4(al[mt], sbase + SM_ALO + off);
            }
            uint2 bh[8], bl[8];
            #pragma unroll
            for (int nt = 0; nt < 8; nt++) {
                bh[nt] = __ldg(&bfh[(ks*8 + nt)*32 + lane]);
                bl[nt] = __ldg(&bfl[(ks*8 + nt)*32 + lane]);
            }
            #pragma unroll
            for (int mt = 0; mt < 2; mt++)
                #pragma unroll
                for (int nt = 0; nt < 8; nt++) {
                    mma16816(acc[mt][nt], ah[mt], bh[nt]);
                    mma16816(acc[mt][nt], al[mt], bh[nt]);
                    mma16816(acc[mt][nt], ah[mt], bl[nt]);
                }
        }
    }

    // epilogue: BN fold + ReLU, direct stores
    #pragma unroll
    for (int nt = 0; nt < 8; nt++) {
        int o0 = nt*8 + ocol;
        float iv0 = g_inv[o0],   bs0 = g_bias2[o0];
        float iv1 = g_inv[o0+1], bs1 = g_bias2[o0+1];
        #pragma unroll
        for (int mt = 0; mt < 2; mt++) {
            #pragma unroll
            for (int half = 0; half < 2; half++) {
                int p = wid*32 + mt*16 + prow + half*8;
                int h = h0 + (p >> 5), w = w0 + (p & 31);
                float* ob = out + ((size_t)b*64*Hc + h)*Wc + w;
                float y0 = acc[mt][nt][half*2]   * iv0 + bs0;
                float y1 = acc[mt][nt][half*2+1] * iv1 + bs1;
                ob[(size_t)o0*HWc]     = fmaxf(y0, 0.f);
                ob[(size_t)(o0+1)*HWc] = fmaxf(y1, 0.f);
            }
        }
    }
}

// ---------------------------------------------------------------------------
extern "C" void kernel_launch(void* const* d_in, const int* in_sizes, int n_in,
                              void* d_out, int out_size) {
    const float* x        = (const float*)d_in[0];
    const float* w_off    = (const float*)d_in[1];
    const float* b_off    = (const float*)d_in[2];
    const float* w_dcn    = (const float*)d_in[3];
    const float* b_dcn    = (const float*)d_in[4];
    const float* gamma    = (const float*)d_in[5];
    const float* beta     = (const float*)d_in[6];
    const float* run_mean = (const float*)d_in[7];
    const float* run_var  = (const float*)d_in[8];
    float* out = (float*)d_out;

    cudaFuncSetAttribute(fused_kernel,
                         cudaFuncAttributeMaxDynamicSharedMemorySize, SM_TOTAL);

    dim3 grid(Wc/32, Hc/8, Bc);
    prep_kernel<<<dim3(9, 4), 256>>>(w_dcn, b_dcn, w_off, gamma, beta, run_mean, run_var);
    transpose_kernel<<<dim3(HWc/64, Bc), 256>>>(x);
    fused_kernel<<<grid, 256, SM_TOTAL>>>(b_off, out);
}